// round 5
// baseline (speedup 1.0000x reference)
#include <cuda_runtime.h>
#include <cuda_bf16.h>

#define L_SEQ 131072
#define H_DIM 256
#define P_DIM 64
#define J_DIM 128
#define T_CH  128
#define NC    (L_SEQ / T_CH)

// ---------------- device scratch ----------------
__device__ float  g_W[H_DIM * J_DIM];              // [h][j], j=2p re / 2p+1 im
__device__ float  g_V[J_DIM * H_DIM];              // [j][h]
__device__ float2 g_Apow[T_CH * P_DIM];            // Lambda_bar^(t+1), [t][p]
__device__ float2 g_LamBar[P_DIM];
__device__ float2 g_Xlocal[(size_t)L_SEQ * P_DIM]; // [t][p]
__device__ float2 g_chunkA[P_DIM * NC];            // [p][c]
__device__ float2 g_chunkB[P_DIM * NC];            // [p][c]
__device__ int    g_chunkFR[NC];
__device__ float2 g_carry[NC * P_DIM];             // [c][p]
__device__ int    g_cntF, g_cntOne, g_cntOther;

// ---------------- helpers ----------------
__device__ __forceinline__ unsigned long long pack2(float x) {
    unsigned long long r;
    asm("mov.b64 %0, {%1, %1};" : "=l"(r) : "f"(x));
    return r;
}
__device__ __forceinline__ void ffma2(unsigned long long& d, unsigned long long a, unsigned long long b) {
    asm("fma.rn.f32x2 %0, %1, %2, %0;" : "+l"(d) : "l"(a), "l"(b));
}
__device__ __forceinline__ float2 unpack2(unsigned long long v) {
    float2 r;
    asm("mov.b64 {%0, %1}, %2;" : "=f"(r.x), "=f"(r.y) : "l"(v));
    return r;
}
__device__ __forceinline__ float2 cmul(float2 a, float2 b) {
    return make_float2(a.x * b.x - a.y * b.y, a.x * b.y + a.y * b.x);
}
__device__ __forceinline__ float2 cexpf2(float re, float im) {
    float e = expf(re), s, c;
    sincosf(im, &s, &c);
    return make_float2(e * c, e * s);
}
__device__ __forceinline__ int d_mode() {
    if (g_cntF > 0) return 2;       // float32
    if (g_cntOther > 0) return 0;   // uint8/bool
    if (g_cntOne > 0) return 1;     // int32
    return 0;
}
__device__ __forceinline__ bool load_d(const void* d, int t, int mode) {
    if (mode == 2) return ((const float*)d)[t] != 0.0f;
    if (mode == 1) return ((const int*)d)[t] != 0;
    return ((const unsigned char*)d)[t] != 0;
}

// ---------------- kernel 0a ----------------
__global__ void zero_flags_kernel() { g_cntF = 0; g_cntOne = 0; g_cntOther = 0; }

// ---------------- kernel 0b: params + d sniff ----------------
__global__ void setup_kernel(const float* __restrict__ Lre, const float* __restrict__ Lim,
                             const float* __restrict__ Bre, const float* __restrict__ Bim,
                             const float* __restrict__ Cre, const float* __restrict__ Cim,
                             const float* __restrict__ deltas,
                             const unsigned* __restrict__ dwords) {
    int g = blockIdx.x * blockDim.x + threadIdx.x;  // 0..32767

    {   // W[h][j] = B_bar = ((exp(lam*dt)-1)/lam) * B
        int h = g >> 7, j = g & 127, p = j >> 1;
        float lre = Lre[p], lim = Lim[p], dp = deltas[p];
        float2 lb = cexpf2(lre * dp, lim * dp);
        float a = lb.x - 1.0f, bb = lb.y;
        float den = lre * lre + lim * lim;
        float cr = (a * lre + bb * lim) / den;
        float ci = (bb * lre - a * lim) / den;
        float br = Bre[p * H_DIM + h], bi = Bim[p * H_DIM + h];
        g_W[h * J_DIM + j] = (j & 1) ? (cr * bi + ci * br) : (cr * br - ci * bi);
    }
    {   // V[j][h]
        int j = g >> 8, h = g & 255, p = j >> 1;
        g_V[j * H_DIM + h] = (j & 1) ? (-2.0f * Cim[h * P_DIM + p]) : (2.0f * Cre[h * P_DIM + p]);
    }
    if (g < P_DIM) {  // Lambda_bar and its powers by repeated multiply (small-arg trig only)
        float2 lam = cexpf2(Lre[g] * deltas[g], Lim[g] * deltas[g]);
        g_LamBar[g] = lam;
        float2 a = lam;
        for (int t = 0; t < T_CH; ++t) {
            g_Apow[t * P_DIM + g] = a;   // lam^(t+1)
            a = cmul(a, lam);
        }
    }
    // d dtype sniff over first 32768 32-bit words
    unsigned w = dwords[g];
    if (w) {
        if (w == 0x3F800000u)  atomicAdd(&g_cntF, 1);
        else if (w == 1u)      atomicAdd(&g_cntOne, 1);
        else                   atomicAdd(&g_cntOther, 1);
    }
}

// ---------------- kernel A: Bu GEMM + local scan ----------------
#define SMEM_A_BYTES ((2 * 16 * 132 + 128 * 128) * 4 + 128)
__global__ __launch_bounds__(256, 2)
void kernelA(const float* __restrict__ u, const void* __restrict__ dflags) {
    extern __shared__ float sm[];
    float* sU  = sm;                         // [16][132]
    float* sW  = sm + 16 * 132;              // [16][132]
    float* sBu = sm + 2 * 16 * 132;          // [128][128]
    unsigned char* sD = (unsigned char*)(sBu + 128 * 128);

    const int c   = blockIdx.x;
    const int tid = threadIdx.x;
    const int tx  = tid & 15, ty = tid >> 4;

    if (tid < T_CH) {
        int mode = d_mode();
        sD[tid] = load_d(dflags, c * T_CH + tid, mode) ? 1 : 0;
    }

    unsigned long long acc[8][4];
#pragma unroll
    for (int r = 0; r < 8; ++r)
#pragma unroll
        for (int q = 0; q < 4; ++q) acc[r][q] = 0ULL;

    for (int ks = 0; ks < 16; ++ks) {
#pragma unroll
        for (int it = 0; it < 2; ++it) {     // stage u: 128t x 16h, transposed
            int idx4 = it * 256 + tid;
            int t = idx4 >> 2, q = idx4 & 3;
            float4 v = *(const float4*)&u[(size_t)(c * T_CH + t) * H_DIM + ks * 16 + q * 4];
            sU[(q * 4 + 0) * 132 + t] = v.x;
            sU[(q * 4 + 1) * 132 + t] = v.y;
            sU[(q * 4 + 2) * 132 + t] = v.z;
            sU[(q * 4 + 3) * 132 + t] = v.w;
        }
#pragma unroll
        for (int it = 0; it < 2; ++it) {     // stage W: 16k x 128j
            int idx4 = it * 256 + tid;
            int kk = idx4 >> 5, j4 = idx4 & 31;
            *(float4*)&sW[kk * 132 + j4 * 4] = *(const float4*)&g_W[(ks * 16 + kk) * J_DIM + j4 * 4];
        }
        __syncthreads();
#pragma unroll
        for (int kk = 0; kk < 16; ++kk) {
            float4 a0 = *(const float4*)&sU[kk * 132 + ty * 8];
            float4 a1 = *(const float4*)&sU[kk * 132 + ty * 8 + 4];
            unsigned long long b2[4];
#pragma unroll
            for (int q = 0; q < 4; ++q)
                b2[q] = *(const unsigned long long*)&sW[kk * 132 + tx * 8 + 2 * q];
            float ar[8] = {a0.x, a0.y, a0.z, a0.w, a1.x, a1.y, a1.z, a1.w};
#pragma unroll
            for (int r = 0; r < 8; ++r) {
                unsigned long long a2 = pack2(ar[r]);
#pragma unroll
                for (int q = 0; q < 4; ++q) ffma2(acc[r][q], a2, b2[q]);
            }
        }
        __syncthreads();
    }

#pragma unroll
    for (int r = 0; r < 8; ++r)
#pragma unroll
        for (int q = 0; q < 4; ++q)
            *(unsigned long long*)&sBu[(ty * 8 + r) * 128 + tx * 8 + 2 * q] = acc[r][q];
    __syncthreads();

    if (tid < P_DIM) {                        // sequential local scan, one state/thread
        const int p = tid;
        const float2 lam = g_LamBar[p];
        float2 A = make_float2(1.0f, 0.0f), b = make_float2(0.0f, 0.0f);
        int fr = T_CH;
        for (int tl = 0; tl < T_CH; ++tl) {
            float2 Bu = *(const float2*)&sBu[tl * 128 + 2 * p];
            if (sD[tl]) {
                A = lam; b = Bu;
                if (fr == T_CH) fr = tl;
            } else {
                float2 nA = cmul(lam, A);
                b = make_float2(lam.x * b.x - lam.y * b.y + Bu.x,
                                lam.x * b.y + lam.y * b.x + Bu.y);
                A = nA;
            }
            g_Xlocal[(size_t)(c * T_CH + tl) * P_DIM + p] = b;
        }
        g_chunkA[p * NC + c] = A;
        g_chunkB[p * NC + c] = b;
        if (p == 0) g_chunkFR[c] = fr;
    }
}

// ---------------- kernel B: chunk-level Kogge-Stone scan ----------------
__global__ __launch_bounds__(1024)
void kernelB(const float* __restrict__ x0re, const float* __restrict__ x0im) {
    __shared__ __align__(16) float2 sA[NC];
    __shared__ __align__(16) float2 sB[NC];
    __shared__ unsigned char sDf[NC];
    const int p = blockIdx.x, c = threadIdx.x;

    float2 A = g_chunkA[p * NC + c];
    float2 b = g_chunkB[p * NC + c];
    unsigned char dflag = (g_chunkFR[c] < T_CH) ? 1 : 0;

    if (c == 0 && !dflag) {                  // fold x0 into chunk 0
        float2 x0 = make_float2(x0re[p], x0im[p]);
        b.x += A.x * x0.x - A.y * x0.y;
        b.y += A.x * x0.y + A.y * x0.x;
    }
    sA[c] = A; sB[c] = b; sDf[c] = dflag;

    for (int off = 1; off < NC; off <<= 1) {
        __syncthreads();
        float2 oA, oB; unsigned char oD = 0;
        bool have = (c >= off);
        if (have) { oA = sA[c - off]; oB = sB[c - off]; oD = sDf[c - off]; }
        __syncthreads();
        if (have && !dflag) {
            b = make_float2(A.x * oB.x - A.y * oB.y + b.x,
                            A.x * oB.y + A.y * oB.x + b.y);
            A = cmul(A, oA);
            dflag = oD;
            sA[c] = A; sB[c] = b; sDf[c] = dflag;
        }
    }
    __syncthreads();
    float2 cv = (c == 0) ? make_float2(x0re[p], x0im[p]) : sB[c - 1];
    g_carry[c * P_DIM + p] = cv;
}

// ---------------- kernel C: correction + output GEMM + epilogue ----------------
__global__ __launch_bounds__(256, 2)
void kernelC(const float* __restrict__ u, const float* __restrict__ Dg, float* __restrict__ y) {
    __shared__ __align__(16) float sX[16 * 132];
    __shared__ __align__(16) float sV[16 * 132];
    __shared__ __align__(16) float2 sCarry[P_DIM];
    __shared__ float sDv[128];
    __shared__ int sFr;

    const int c     = blockIdx.x;
    const int hbase = blockIdx.y * 128;
    const int tid   = threadIdx.x;
    const int tx    = tid & 15, ty = tid >> 4;

    if (tid < P_DIM) sCarry[tid] = g_carry[c * P_DIM + tid];
    if (tid < 128)   sDv[tid]    = Dg[hbase + tid];
    if (tid == 0)    sFr         = g_chunkFR[c];

    unsigned long long acc[8][4];
#pragma unroll
    for (int r = 0; r < 8; ++r)
#pragma unroll
        for (int q = 0; q < 4; ++q) acc[r][q] = 0ULL;

    __syncthreads();
    const int fr = sFr;

    for (int ks = 0; ks < 8; ++ks) {
#pragma unroll
        for (int it = 0; it < 4; ++it) {     // stage corrected x: 128t x 8 complex states
            int idx = it * 256 + tid;
            int t = idx >> 3, pp = idx & 7;
            int p = ks * 8 + pp;
            float2 xl = g_Xlocal[(size_t)(c * T_CH + t) * P_DIM + p];
            if (t < fr) {
                float2 ap = g_Apow[t * P_DIM + p];
                float2 cv = sCarry[p];
                xl.x += ap.x * cv.x - ap.y * cv.y;
                xl.y += ap.x * cv.y + ap.y * cv.x;
            }
            sX[(2 * pp + 0) * 132 + t] = xl.x;
            sX[(2 * pp + 1) * 132 + t] = xl.y;
        }
#pragma unroll
        for (int it = 0; it < 2; ++it) {     // stage V: 16k x 128h
            int idx4 = it * 256 + tid;
            int kk = idx4 >> 5, h4 = idx4 & 31;
            *(float4*)&sV[kk * 132 + h4 * 4] =
                *(const float4*)&g_V[(ks * 16 + kk) * H_DIM + hbase + h4 * 4];
        }
        __syncthreads();
#pragma unroll
        for (int kk = 0; kk < 16; ++kk) {
            float4 a0 = *(const float4*)&sX[kk * 132 + ty * 8];
            float4 a1 = *(const float4*)&sX[kk * 132 + ty * 8 + 4];
            unsigned long long b2[4];
#pragma unroll
            for (int q = 0; q < 4; ++q)
                b2[q] = *(const unsigned long long*)&sV[kk * 132 + tx * 8 + 2 * q];
            float ar[8] = {a0.x, a0.y, a0.z, a0.w, a1.x, a1.y, a1.z, a1.w};
#pragma unroll
            for (int r = 0; r < 8; ++r) {
                unsigned long long a2 = pack2(ar[r]);
#pragma unroll
                for (int q = 0; q < 4; ++q) ffma2(acc[r][q], a2, b2[q]);
            }
        }
        __syncthreads();
    }

    // epilogue: y = acc + u*D, float4 stores
#pragma unroll
    for (int r = 0; r < 8; ++r) {
        size_t t = (size_t)c * T_CH + ty * 8 + r;
        const float* urow = &u[t * H_DIM + hbase + tx * 8];
        float4 u0 = *(const float4*)urow;
        float4 u1 = *(const float4*)(urow + 4);
        float2 a0 = unpack2(acc[r][0]), a1 = unpack2(acc[r][1]);
        float2 a2 = unpack2(acc[r][2]), a3 = unpack2(acc[r][3]);
        int hb = tx * 8;
        float4 o0 = make_float4(a0.x + u0.x * sDv[hb + 0], a0.y + u0.y * sDv[hb + 1],
                                a1.x + u0.z * sDv[hb + 2], a1.y + u0.w * sDv[hb + 3]);
        float4 o1 = make_float4(a2.x + u1.x * sDv[hb + 4], a2.y + u1.y * sDv[hb + 5],
                                a3.x + u1.z * sDv[hb + 6], a3.y + u1.w * sDv[hb + 7]);
        float* yrow = &y[t * H_DIM + hbase + tx * 8];
        *(float4*)yrow = o0;
        *(float4*)(yrow + 4) = o1;
    }
}

// ---------------- launch ----------------
extern "C" void kernel_launch(void* const* d_in, const int* in_sizes, int n_in,
                              void* d_out, int out_size) {
    (void)in_sizes; (void)n_in; (void)out_size;
    const float* u     = (const float*)d_in[0];
    const float* Lre   = (const float*)d_in[1];
    const float* Lim   = (const float*)d_in[2];
    const float* Bre   = (const float*)d_in[3];
    const float* Bim   = (const float*)d_in[4];
    const float* Cre   = (const float*)d_in[5];
    const float* Cim   = (const float*)d_in[6];
    const float* Dv    = (const float*)d_in[7];
    const float* delt  = (const float*)d_in[8];
    const float* x0re  = (const float*)d_in[9];
    const float* x0im  = (const float*)d_in[10];
    const void*  dfl   = d_in[11];
    float* y = (float*)d_out;

    static bool attr_set = false;
    if (!attr_set) {
        cudaFuncSetAttribute(kernelA, cudaFuncAttributeMaxDynamicSharedMemorySize, SMEM_A_BYTES);
        attr_set = true;
    }

    zero_flags_kernel<<<1, 1>>>();
    setup_kernel<<<128, 256>>>(Lre, Lim, Bre, Bim, Cre, Cim, delt, (const unsigned*)dfl);
    kernelA<<<NC, 256, SMEM_A_BYTES>>>(u, dfl);
    kernelB<<<P_DIM, NC>>>(x0re, x0im);
    kernelC<<<dim3(NC, 2), 256>>>(u, Dv, y);
}

// round 7
// speedup vs baseline: 1.1640x; 1.1640x over previous
#include <cuda_runtime.h>
#include <cuda_bf16.h>

#define L_SEQ 131072
#define H_DIM 256
#define P_DIM 64
#define J_DIM 128
#define T_CH  128
#define NC    (L_SEQ / T_CH)

// ---------------- device scratch ----------------
__device__ float  g_W[H_DIM * J_DIM];              // [h][j], j=2p re / 2p+1 im
__device__ float  g_V[J_DIM * H_DIM];              // [j][h]
__device__ float2 g_Apow[T_CH * P_DIM];            // Lambda_bar^(t+1), [t][p]
__device__ float2 g_LamBar[P_DIM];
__device__ float2 g_Xlocal[(size_t)L_SEQ * P_DIM]; // [t][p]
__device__ float2 g_chunkA[P_DIM * NC];            // [p][c]
__device__ float2 g_chunkB[P_DIM * NC];            // [p][c]
__device__ int    g_chunkFR[NC];
__device__ float2 g_carry[NC * P_DIM];             // [c][p]
__device__ int    g_cntF, g_cntOne, g_cntOther;

// ---------------- helpers ----------------
__device__ __forceinline__ unsigned long long pack2(float x) {
    unsigned long long r;
    asm("mov.b64 %0, {%1, %1};" : "=l"(r) : "f"(x));
    return r;
}
__device__ __forceinline__ void ffma2(unsigned long long& d, unsigned long long a, unsigned long long b) {
    asm("fma.rn.f32x2 %0, %1, %2, %0;" : "+l"(d) : "l"(a), "l"(b));
}
__device__ __forceinline__ float2 unpack2(unsigned long long v) {
    float2 r;
    asm("mov.b64 {%0, %1}, %2;" : "=f"(r.x), "=f"(r.y) : "l"(v));
    return r;
}
__device__ __forceinline__ float2 cmul(float2 a, float2 b) {
    return make_float2(a.x * b.x - a.y * b.y, a.x * b.y + a.y * b.x);
}
__device__ __forceinline__ float2 cexpf2(float re, float im) {
    float e = expf(re), s, c;
    sincosf(im, &s, &c);
    return make_float2(e * c, e * s);
}
__device__ __forceinline__ int d_mode() {
    if (g_cntF > 0) return 2;       // float32
    if (g_cntOther > 0) return 0;   // uint8/bool
    if (g_cntOne > 0) return 1;     // int32
    return 0;
}
__device__ __forceinline__ bool load_d(const void* d, int t, int mode) {
    if (mode == 2) return ((const float*)d)[t] != 0.0f;
    if (mode == 1) return ((const int*)d)[t] != 0;
    return ((const unsigned char*)d)[t] != 0;
}

// ---------------- kernel 0a ----------------
__global__ void zero_flags_kernel() { g_cntF = 0; g_cntOne = 0; g_cntOther = 0; }

// ---------------- kernel 0b: params + d sniff ----------------
__global__ void setup_kernel(const float* __restrict__ Lre, const float* __restrict__ Lim,
                             const float* __restrict__ Bre, const float* __restrict__ Bim,
                             const float* __restrict__ Cre, const float* __restrict__ Cim,
                             const float* __restrict__ deltas,
                             const unsigned* __restrict__ dwords) {
    int g = blockIdx.x * blockDim.x + threadIdx.x;  // 0..32767

    {   // W[h][j] = B_bar = ((exp(lam*dt)-1)/lam) * B
        int h = g >> 7, j = g & 127, p = j >> 1;
        float lre = Lre[p], lim = Lim[p], dp = deltas[p];
        float2 lb = cexpf2(lre * dp, lim * dp);
        float a = lb.x - 1.0f, bb = lb.y;
        float den = lre * lre + lim * lim;
        float cr = (a * lre + bb * lim) / den;
        float ci = (bb * lre - a * lim) / den;
        float br = Bre[p * H_DIM + h], bi = Bim[p * H_DIM + h];
        g_W[h * J_DIM + j] = (j & 1) ? (cr * bi + ci * br) : (cr * br - ci * bi);
    }
    {   // V[j][h]
        int j = g >> 8, h = g & 255, p = j >> 1;
        g_V[j * H_DIM + h] = (j & 1) ? (-2.0f * Cim[h * P_DIM + p]) : (2.0f * Cre[h * P_DIM + p]);
    }
    if (g < P_DIM) {  // Lambda_bar and its powers by repeated multiply
        float2 lam = cexpf2(Lre[g] * deltas[g], Lim[g] * deltas[g]);
        g_LamBar[g] = lam;
        float2 a = lam;
        for (int t = 0; t < T_CH; ++t) {
            g_Apow[t * P_DIM + g] = a;   // lam^(t+1)
            a = cmul(a, lam);
        }
    }
    // d dtype sniff over first 32768 32-bit words
    unsigned w = dwords[g];
    if (w) {
        if (w == 0x3F800000u)  atomicAdd(&g_cntF, 1);
        else if (w == 1u)      atomicAdd(&g_cntOne, 1);
        else                   atomicAdd(&g_cntOther, 1);
    }
}

// ---------------- kernel A: Bu GEMM + local scan ----------------
// Thread output mapping (bank-conflict-free): columns j = 2*tx + 32*q, q=0..3
#define SMEM_A_BYTES ((2 * 16 * 132 + 128 * 128) * 4 + 128)
__global__ __launch_bounds__(256, 2)
void kernelA(const float* __restrict__ u, const void* __restrict__ dflags) {
    extern __shared__ float sm[];
    float* sU  = sm;                         // [16][132] transposed u
    float* sW  = sm + 16 * 132;              // [16][132]
    float* sBu = sm + 2 * 16 * 132;          // [128][128]
    unsigned char* sD = (unsigned char*)(sBu + 128 * 128);

    const int c   = blockIdx.x;
    const int tid = threadIdx.x;
    const int tx  = tid & 15, ty = tid >> 4;

    if (tid < T_CH) {
        int mode = d_mode();
        sD[tid] = load_d(dflags, c * T_CH + tid, mode) ? 1 : 0;
    }

    unsigned long long acc[8][4];
#pragma unroll
    for (int r = 0; r < 8; ++r)
#pragma unroll
        for (int q = 0; q < 4; ++q) acc[r][q] = 0ULL;

    for (int ks = 0; ks < 16; ++ks) {
#pragma unroll
        for (int it = 0; it < 2; ++it) {     // stage u: 128t x 16h, transposed
            int idx4 = it * 256 + tid;
            int t = idx4 >> 2, q = idx4 & 3;
            float4 v = *(const float4*)&u[(size_t)(c * T_CH + t) * H_DIM + ks * 16 + q * 4];
            sU[(q * 4 + 0) * 132 + t] = v.x;
            sU[(q * 4 + 1) * 132 + t] = v.y;
            sU[(q * 4 + 2) * 132 + t] = v.z;
            sU[(q * 4 + 3) * 132 + t] = v.w;
        }
#pragma unroll
        for (int it = 0; it < 2; ++it) {     // stage W: 16k x 128j
            int idx4 = it * 256 + tid;
            int kk = idx4 >> 5, j4 = idx4 & 31;
            *(float4*)&sW[kk * 132 + j4 * 4] = *(const float4*)&g_W[(ks * 16 + kk) * J_DIM + j4 * 4];
        }
        __syncthreads();
#pragma unroll
        for (int kk = 0; kk < 16; ++kk) {
            float4 a0 = *(const float4*)&sU[kk * 132 + ty * 8];       // broadcast
            float4 a1 = *(const float4*)&sU[kk * 132 + ty * 8 + 4];
            unsigned long long b2[4];
#pragma unroll
            for (int q = 0; q < 4; ++q)                               // conflict-free: stride 8B
                b2[q] = *(const unsigned long long*)&sW[kk * 132 + 2 * tx + 32 * q];
            float ar[8] = {a0.x, a0.y, a0.z, a0.w, a1.x, a1.y, a1.z, a1.w};
#pragma unroll
            for (int r = 0; r < 8; ++r) {
                unsigned long long a2 = pack2(ar[r]);
#pragma unroll
                for (int q = 0; q < 4; ++q) ffma2(acc[r][q], a2, b2[q]);
            }
        }
        __syncthreads();
    }

#pragma unroll
    for (int r = 0; r < 8; ++r)
#pragma unroll
        for (int q = 0; q < 4; ++q)
            *(unsigned long long*)&sBu[(ty * 8 + r) * 128 + 2 * tx + 32 * q] = acc[r][q];
    __syncthreads();

    if (tid < P_DIM) {                        // sequential local scan, one state/thread
        const int p = tid;
        const float2 lam = g_LamBar[p];
        float2 A = make_float2(1.0f, 0.0f), b = make_float2(0.0f, 0.0f);
        int fr = T_CH;
        for (int tl = 0; tl < T_CH; ++tl) {
            float2 Bu = *(const float2*)&sBu[tl * 128 + 2 * p];
            if (sD[tl]) {
                A = lam; b = Bu;
                if (fr == T_CH) fr = tl;
            } else {
                float2 nA = cmul(lam, A);
                b = make_float2(lam.x * b.x - lam.y * b.y + Bu.x,
                                lam.x * b.y + lam.y * b.x + Bu.y);
                A = nA;
            }
            g_Xlocal[(size_t)(c * T_CH + tl) * P_DIM + p] = b;
        }
        g_chunkA[p * NC + c] = A;
        g_chunkB[p * NC + c] = b;
        if (p == 0) g_chunkFR[c] = fr;
    }
}

// ---------------- kernel B: chunk-level Kogge-Stone scan ----------------
__global__ __launch_bounds__(1024)
void kernelB(const float* __restrict__ x0re, const float* __restrict__ x0im) {
    __shared__ __align__(16) float2 sA[NC];
    __shared__ __align__(16) float2 sB[NC];
    __shared__ unsigned char sDf[NC];
    const int p = blockIdx.x, c = threadIdx.x;

    float2 A = g_chunkA[p * NC + c];
    float2 b = g_chunkB[p * NC + c];
    unsigned char dflag = (g_chunkFR[c] < T_CH) ? 1 : 0;

    if (c == 0 && !dflag) {                  // fold x0 into chunk 0
        float2 x0 = make_float2(x0re[p], x0im[p]);
        b.x += A.x * x0.x - A.y * x0.y;
        b.y += A.x * x0.y + A.y * x0.x;
    }
    sA[c] = A; sB[c] = b; sDf[c] = dflag;

    for (int off = 1; off < NC; off <<= 1) {
        __syncthreads();
        float2 oA, oB; unsigned char oD = 0;
        bool have = (c >= off);
        if (have) { oA = sA[c - off]; oB = sB[c - off]; oD = sDf[c - off]; }
        __syncthreads();
        if (have && !dflag) {
            b = make_float2(A.x * oB.x - A.y * oB.y + b.x,
                            A.x * oB.y + A.y * oB.x + b.y);
            A = cmul(A, oA);
            dflag = oD;
            sA[c] = A; sB[c] = b; sDf[c] = dflag;
        }
    }
    __syncthreads();
    float2 cv = (c == 0) ? make_float2(x0re[p], x0im[p]) : sB[c - 1];
    g_carry[c * P_DIM + p] = cv;
}

// ---------------- kernel C: correction + output GEMM + epilogue ----------------
__global__ __launch_bounds__(256, 2)
void kernelC(const float* __restrict__ u, const float* __restrict__ Dg, float* __restrict__ y) {
    __shared__ __align__(16) float sX[16 * 132];
    __shared__ __align__(16) float sV[16 * 132];
    __shared__ __align__(16) float2 sCarry[P_DIM];
    __shared__ float sDv[128];
    __shared__ int sFr;

    const int c     = blockIdx.x;
    const int hbase = blockIdx.y * 128;
    const int tid   = threadIdx.x;
    const int tx    = tid & 15, ty = tid >> 4;

    if (tid < P_DIM) sCarry[tid] = g_carry[c * P_DIM + tid];
    if (tid < 128)   sDv[tid]    = Dg[hbase + tid];
    if (tid == 0)    sFr         = g_chunkFR[c];

    unsigned long long acc[8][4];
#pragma unroll
    for (int r = 0; r < 8; ++r)
#pragma unroll
        for (int q = 0; q < 4; ++q) acc[r][q] = 0ULL;

    __syncthreads();
    const int fr = sFr;

    for (int ks = 0; ks < 8; ++ks) {
#pragma unroll
        for (int it = 0; it < 4; ++it) {     // stage corrected x: 128t x 8 complex states
            int idx = it * 256 + tid;
            int t = idx >> 3, pp = idx & 7;
            int p = ks * 8 + pp;
            float2 xl = g_Xlocal[(size_t)(c * T_CH + t) * P_DIM + p];
            if (t < fr) {
                float2 ap = g_Apow[t * P_DIM + p];
                float2 cv = sCarry[p];
                xl.x += ap.x * cv.x - ap.y * cv.y;
                xl.y += ap.x * cv.y + ap.y * cv.x;
            }
            sX[(2 * pp + 0) * 132 + t] = xl.x;
            sX[(2 * pp + 1) * 132 + t] = xl.y;
        }
#pragma unroll
        for (int it = 0; it < 2; ++it) {     // stage V: 16k x 128h
            int idx4 = it * 256 + tid;
            int kk = idx4 >> 5, h4 = idx4 & 31;
            *(float4*)&sV[kk * 132 + h4 * 4] =
                *(const float4*)&g_V[(ks * 16 + kk) * H_DIM + hbase + h4 * 4];
        }
        __syncthreads();
#pragma unroll
        for (int kk = 0; kk < 16; ++kk) {
            float4 a0 = *(const float4*)&sX[kk * 132 + ty * 8];       // broadcast
            float4 a1 = *(const float4*)&sX[kk * 132 + ty * 8 + 4];
            unsigned long long b2[4];
#pragma unroll
            for (int q = 0; q < 4; ++q)                               // conflict-free
                b2[q] = *(const unsigned long long*)&sV[kk * 132 + 2 * tx + 32 * q];
            float ar[8] = {a0.x, a0.y, a0.z, a0.w, a1.x, a1.y, a1.z, a1.w};
#pragma unroll
            for (int r = 0; r < 8; ++r) {
                unsigned long long a2 = pack2(ar[r]);
#pragma unroll
                for (int q = 0; q < 4; ++q) ffma2(acc[r][q], a2, b2[q]);
            }
        }
        __syncthreads();
    }

    // epilogue: y = acc + u*D, columns h = 2*tx + 32*q (+0/1), float2 ops (coalesced)
#pragma unroll
    for (int r = 0; r < 8; ++r) {
        size_t t = (size_t)c * T_CH + ty * 8 + r;
#pragma unroll
        for (int q = 0; q < 4; ++q) {
            int hl = 2 * tx + 32 * q;
            float2 uv = *(const float2*)&u[t * H_DIM + hbase + hl];
            float2 a  = unpack2(acc[r][q]);
            float2 o  = make_float2(a.x + uv.x * sDv[hl],
                                    a.y + uv.y * sDv[hl + 1]);
            *(float2*)&y[t * H_DIM + hbase + hl] = o;
        }
    }
}

// ---------------- launch ----------------
extern "C" void kernel_launch(void* const* d_in, const int* in_sizes, int n_in,
                              void* d_out, int out_size) {
    (void)in_sizes; (void)n_in; (void)out_size;
    const float* u     = (const float*)d_in[0];
    const float* Lre   = (const float*)d_in[1];
    const float* Lim   = (const float*)d_in[2];
    const float* Bre   = (const float*)d_in[3];
    const float* Bim   = (const float*)d_in[4];
    const float* Cre   = (const float*)d_in[5];
    const float* Cim   = (const float*)d_in[6];
    const float* Dv    = (const float*)d_in[7];
    const float* delt  = (const float*)d_in[8];
    const float* x0re  = (const float*)d_in[9];
    const float* x0im  = (const float*)d_in[10];
    const void*  dfl   = d_in[11];
    float* y = (float*)d_out;

    static bool attr_set = false;
    if (!attr_set) {
        cudaFuncSetAttribute(kernelA, cudaFuncAttributeMaxDynamicSharedMemorySize, SMEM_A_BYTES);
        attr_set = true;
    }

    zero_flags_kernel<<<1, 1>>>();
    setup_kernel<<<128, 256>>>(Lre, Lim, Bre, Bim, Cre, Cim, delt, (const unsigned*)dfl);
    kernelA<<<NC, 256, SMEM_A_BYTES>>>(u, dfl);
    kernelB<<<P_DIM, NC>>>(x0re, x0im);
    kernelC<<<dim3(NC, 2), 256>>>(u, Dv, y);
}

// round 12
// speedup vs baseline: 1.2891x; 1.1075x over previous
#include <cuda_runtime.h>
#include <cuda_bf16.h>
#include <cstdint>

#define L_SEQ 131072
#define H_DIM 256
#define P_DIM 64
#define J_DIM 128
#define T_CH  128
#define NC    (L_SEQ / T_CH)

// ================= device scratch =================
// W tile images for HMMA kernelA: [K-half][hi/lo] of [128 j rows][136 k cols] bf16 (34816 B each)
__device__ float4 g_WTiles[4 * 2176];
__device__ float  g_V[J_DIM * H_DIM];               // [j][h] f32 (for FFMA2 kernelC)
__device__ float2 g_Apow[T_CH * P_DIM];             // [t][p] lam^(t+1) (for kernelC)
__device__ float2 g_LamBar[P_DIM];
__device__ float4 g_Xlocal[(size_t)L_SEQ * P_DIM / 2];
__device__ float2 g_chunkA[P_DIM * NC];
__device__ float2 g_chunkB[P_DIM * NC];
__device__ int    g_chunkFR[NC];
__device__ float2 g_carry[NC * P_DIM];
__device__ int    g_cntF, g_cntOne, g_cntOther;

// ================= helpers =================
__device__ __forceinline__ float2 cmul(float2 a, float2 b) {
    return make_float2(a.x * b.x - a.y * b.y, a.x * b.y + a.y * b.x);
}
__device__ __forceinline__ float2 cexpf2(float re, float im) {
    float e = expf(re), s, c;
    sincosf(im, &s, &c);
    return make_float2(e * c, e * s);
}
__device__ __forceinline__ int d_mode() {
    if (g_cntF > 0) return 2;
    if (g_cntOther > 0) return 0;
    if (g_cntOne > 0) return 1;
    return 0;
}
__device__ __forceinline__ bool load_d(const void* d, int t, int mode) {
    if (mode == 2) return ((const float*)d)[t] != 0.0f;
    if (mode == 1) return ((const int*)d)[t] != 0;
    return ((const unsigned char*)d)[t] != 0;
}
// FFMA2 helpers (proven in R5/R7)
__device__ __forceinline__ unsigned long long pack2(float x) {
    unsigned long long r;
    asm("mov.b64 %0, {%1, %1};" : "=l"(r) : "f"(x));
    return r;
}
__device__ __forceinline__ void ffma2(unsigned long long& d, unsigned long long a, unsigned long long b) {
    asm("fma.rn.f32x2 %0, %1, %2, %0;" : "+l"(d) : "l"(a), "l"(b));
}
__device__ __forceinline__ float2 unpack2(unsigned long long v) {
    float2 r;
    asm("mov.b64 {%0, %1}, %2;" : "=f"(r.x), "=f"(r.y) : "l"(v));
    return r;
}
// HMMA helpers
__device__ __forceinline__ uint32_t split_pair(float a, float b, uint32_t& lo_pack) {
    __nv_bfloat16 ah = __float2bfloat16(a), bh = __float2bfloat16(b);
    float ar = a - __bfloat162float(ah), br = b - __bfloat162float(bh);
    __nv_bfloat16 al = __float2bfloat16(ar), bl = __float2bfloat16(br);
    lo_pack = ((uint32_t)__bfloat16_as_ushort(bl) << 16) | (uint32_t)__bfloat16_as_ushort(al);
    return ((uint32_t)__bfloat16_as_ushort(bh) << 16) | (uint32_t)__bfloat16_as_ushort(ah);
}
__device__ __forceinline__ void mma16816(float c[4], const uint32_t a[4], uint32_t b0, uint32_t b1) {
    asm volatile("mma.sync.aligned.m16n8k16.row.col.f32.bf16.bf16.f32 "
                 "{%0,%1,%2,%3}, {%4,%5,%6,%7}, {%8,%9}, {%0,%1,%2,%3};"
                 : "+f"(c[0]), "+f"(c[1]), "+f"(c[2]), "+f"(c[3])
                 : "r"(a[0]), "r"(a[1]), "r"(a[2]), "r"(a[3]), "r"(b0), "r"(b1));
}
// K=128 pass: A [128][136] bf16 row-major (k contig), B [128 n][136] (k contig). Warp tile 32x64.
__device__ __forceinline__ void mma_pass(const __nv_bfloat16* As, const __nv_bfloat16* Bs,
                                         float acc[2][8][4], int wm, int wn, int gq, int tg) {
#pragma unroll 2
    for (int kk = 0; kk < 8; ++kk) {
        const int k0 = kk * 16 + 2 * tg;
        uint32_t af[2][4];
#pragma unroll
        for (int fm = 0; fm < 2; ++fm) {
            int r = wm * 32 + fm * 16 + gq;
            af[fm][0] = *(const uint32_t*)&As[r * 136 + k0];
            af[fm][1] = *(const uint32_t*)&As[(r + 8) * 136 + k0];
            af[fm][2] = *(const uint32_t*)&As[r * 136 + k0 + 8];
            af[fm][3] = *(const uint32_t*)&As[(r + 8) * 136 + k0 + 8];
        }
#pragma unroll
        for (int fn = 0; fn < 8; ++fn) {
            int n = wn * 64 + fn * 8 + gq;
            uint32_t b0 = *(const uint32_t*)&Bs[n * 136 + k0];
            uint32_t b1 = *(const uint32_t*)&Bs[n * 136 + k0 + 8];
            mma16816(acc[0][fn], af[0], b0, b1);
            mma16816(acc[1][fn], af[1], b0, b1);
        }
    }
}

// ================= kernel 0a =================
__global__ void zero_flags_kernel() { g_cntF = 0; g_cntOne = 0; g_cntOther = 0; }

// ================= kernel 0b: params + both operand formats + d sniff =================
__global__ void setup_kernel(const float* __restrict__ Lre, const float* __restrict__ Lim,
                             const float* __restrict__ Bre, const float* __restrict__ Bim,
                             const float* __restrict__ Cre, const float* __restrict__ Cim,
                             const float* __restrict__ deltas,
                             const unsigned* __restrict__ dwords) {
    int g = blockIdx.x * blockDim.x + threadIdx.x;   // 0..32767

    {   // W element (h, j) -> bf16 hi/lo tile images (rows=j, cols=k=h within K-half)
        int h = g >> 7, j = g & 127, p = j >> 1;
        float lre = Lre[p], lim = Lim[p], dp = deltas[p];
        float2 lb = cexpf2(lre * dp, lim * dp);
        float a = lb.x - 1.0f, bb = lb.y;
        float den = lre * lre + lim * lim;
        float cr = (a * lre + bb * lim) / den;
        float ci = (bb * lre - a * lim) / den;
        float br = Bre[p * H_DIM + h], bi = Bim[p * H_DIM + h];
        float Wv = (j & 1) ? (cr * bi + ci * br) : (cr * br - ci * bi);
        __nv_bfloat16 hi = __float2bfloat16(Wv);
        __nv_bfloat16 lo = __float2bfloat16(Wv - __bfloat162float(hi));
        int kh = h >> 7, col = h & 127;
        char* wb = (char*)g_WTiles;
        uint32_t off = (uint32_t)(kh * 2) * 34816u + (uint32_t)j * 272u + (uint32_t)col * 2u;
        *(__nv_bfloat16*)(wb + off)          = hi;
        *(__nv_bfloat16*)(wb + off + 34816u) = lo;
    }
    {   // V[j][h] f32 (for FFMA2 kernelC)
        int j = g >> 8, h = g & 255, p = j >> 1;
        g_V[j * H_DIM + h] = (j & 1) ? (-2.0f * Cim[h * P_DIM + p]) : (2.0f * Cre[h * P_DIM + p]);
    }
    if (g < P_DIM) {
        float2 lam = cexpf2(Lre[g] * deltas[g], Lim[g] * deltas[g]);
        g_LamBar[g] = lam;
        float2 a = lam;
        for (int t = 0; t < T_CH; ++t) {
            g_Apow[t * P_DIM + g] = a;   // lam^(t+1)
            a = cmul(a, lam);
        }
    }
    unsigned w = dwords[g];
    if (w) {
        if (w == 0x3F800000u)  atomicAdd(&g_cntF, 1);
        else if (w == 1u)      atomicAdd(&g_cntOne, 1);
        else                   atomicAdd(&g_cntOther, 1);
    }
}

// ================= kernel A: Bu HMMA GEMM + local scan =================
// smem: [0..1024) hdr (sD @16); uh @1024; ul @35840; Wb @70656; total 105472.
// sBu (f32 [128][132], 67584 B) overlays uh/ul after the MMAs.
#define A_UH  1024
#define A_UL  (A_UH + 34816)
#define A_WB  (A_UL + 34816)
#define A_TOT (A_WB + 34816)
__global__ __launch_bounds__(256)
void kernelA(const float* __restrict__ u, const void* __restrict__ dflags) {
    extern __shared__ char smem[];
    unsigned char* sD = (unsigned char*)(smem + 16);
    __nv_bfloat16* uh = (__nv_bfloat16*)(smem + A_UH);
    __nv_bfloat16* ul = (__nv_bfloat16*)(smem + A_UL);
    __nv_bfloat16* Wb = (__nv_bfloat16*)(smem + A_WB);
    float* sBu = (float*)(smem + A_UH);

    const int tid = threadIdx.x, wid = tid >> 5, lane = tid & 31;
    const int wm = wid & 3, wn = wid >> 2;
    const int gq = lane >> 2, tg = lane & 3;
    const int c = blockIdx.x;

    if (tid < T_CH) {
        int mode = d_mode();
        sD[tid] = load_d(dflags, c * T_CH + tid, mode) ? 1 : 0;
    }

    float acc[2][8][4];
#pragma unroll
    for (int fm = 0; fm < 2; ++fm)
#pragma unroll
        for (int fn = 0; fn < 8; ++fn)
#pragma unroll
            for (int q = 0; q < 4; ++q) acc[fm][fn][q] = 0.0f;

    for (int kh = 0; kh < 2; ++kh) {
        __syncthreads();                         // prior readers of uh/ul/Wb done
        {   // stage W hi image for this K-half
            const float4* src = g_WTiles + (kh * 2 + 0) * 2176;
            float4* dst = (float4*)(smem + A_WB);
            for (int i = tid; i < 2176; i += 256) dst[i] = src[i];
        }
        // convert u K-half -> uh/ul (scalar 32-bit smem stores)
        for (int i = tid; i < 4096; i += 256) {
            int t = i >> 5, q = i & 31;
            float4 v = *(const float4*)&u[(size_t)(c * T_CH + t) * H_DIM + kh * 128 + 4 * q];
            uint32_t l0, l1;
            uint32_t h0 = split_pair(v.x, v.y, l0);
            uint32_t h1 = split_pair(v.z, v.w, l1);
            *(uint32_t*)&uh[t * 136 + 4 * q]     = h0;
            *(uint32_t*)&uh[t * 136 + 4 * q + 2] = h1;
            *(uint32_t*)&ul[t * 136 + 4 * q]     = l0;
            *(uint32_t*)&ul[t * 136 + 4 * q + 2] = l1;
        }
        __syncthreads();
        mma_pass(uh, Wb, acc, wm, wn, gq, tg);   // hi*hi
        mma_pass(ul, Wb, acc, wm, wn, gq, tg);   // lo*hi
        __syncthreads();
        {   // stage W lo image
            const float4* src = g_WTiles + (kh * 2 + 1) * 2176;
            float4* dst = (float4*)(smem + A_WB);
            for (int i = tid; i < 2176; i += 256) dst[i] = src[i];
        }
        __syncthreads();
        mma_pass(uh, Wb, acc, wm, wn, gq, tg);   // hi*lo
    }
    __syncthreads();                             // uh/ul now dead -> overlay sBu

#pragma unroll
    for (int fm = 0; fm < 2; ++fm) {
        int r0 = wm * 32 + fm * 16 + gq;
#pragma unroll
        for (int fn = 0; fn < 8; ++fn) {
            int nb = wn * 64 + fn * 8 + 2 * tg;
            *(float2*)&sBu[r0 * 132 + nb]       = make_float2(acc[fm][fn][0], acc[fm][fn][1]);
            *(float2*)&sBu[(r0 + 8) * 132 + nb] = make_float2(acc[fm][fn][2], acc[fm][fn][3]);
        }
    }
    __syncthreads();

    if (tid < P_DIM) {                           // sequential local scan
        const int p = tid;
        const float2 lam = g_LamBar[p];
        float2 A = make_float2(1.0f, 0.0f), b = make_float2(0.0f, 0.0f);
        int fr = T_CH;
        float2* xl = (float2*)g_Xlocal;
        for (int tl = 0; tl < T_CH; ++tl) {
            float2 Bu = *(const float2*)&sBu[tl * 132 + 2 * p];
            if (sD[tl]) {
                A = lam; b = Bu;
                if (fr == T_CH) fr = tl;
            } else {
                float2 nA = cmul(lam, A);
                b = make_float2(lam.x * b.x - lam.y * b.y + Bu.x,
                                lam.x * b.y + lam.y * b.x + Bu.y);
                A = nA;
            }
            xl[(size_t)(c * T_CH + tl) * P_DIM + p] = b;
        }
        g_chunkA[p * NC + c] = A;
        g_chunkB[p * NC + c] = b;
        if (p == 0) g_chunkFR[c] = fr;
    }
}

// ================= kernel B: chunk-level Kogge-Stone scan =================
__global__ __launch_bounds__(1024)
void kernelB(const float* __restrict__ x0re, const float* __restrict__ x0im) {
    __shared__ __align__(16) float2 sA[NC];
    __shared__ __align__(16) float2 sB[NC];
    __shared__ unsigned char sDf[NC];
    const int p = blockIdx.x, c = threadIdx.x;

    float2 A = g_chunkA[p * NC + c];
    float2 b = g_chunkB[p * NC + c];
    unsigned char dflag = (g_chunkFR[c] < T_CH) ? 1 : 0;

    if (c == 0 && !dflag) {
        float2 x0 = make_float2(x0re[p], x0im[p]);
        b.x += A.x * x0.x - A.y * x0.y;
        b.y += A.x * x0.y + A.y * x0.x;
    }
    sA[c] = A; sB[c] = b; sDf[c] = dflag;

    for (int off = 1; off < NC; off <<= 1) {
        __syncthreads();
        float2 oA, oB; unsigned char oD = 0;
        bool have = (c >= off);
        if (have) { oA = sA[c - off]; oB = sB[c - off]; oD = sDf[c - off]; }
        __syncthreads();
        if (have && !dflag) {
            b = make_float2(A.x * oB.x - A.y * oB.y + b.x,
                            A.x * oB.y + A.y * oB.x + b.y);
            A = cmul(A, oA);
            dflag = oD;
            sA[c] = A; sB[c] = b; sDf[c] = dflag;
        }
    }
    __syncthreads();
    float2 cv = (c == 0) ? make_float2(x0re[p], x0im[p]) : sB[c - 1];
    g_carry[c * P_DIM + p] = cv;
}

// ================= kernel C: FFMA2 version (verbatim R7, proven) =================
__global__ __launch_bounds__(256, 2)
void kernelC(const float* __restrict__ u, const float* __restrict__ Dg, float* __restrict__ y) {
    __shared__ __align__(16) float sX[16 * 132];
    __shared__ __align__(16) float sV[16 * 132];
    __shared__ __align__(16) float2 sCarry[P_DIM];
    __shared__ float sDv[128];
    __shared__ int sFr;

    const int c     = blockIdx.x;
    const int hbase = blockIdx.y * 128;
    const int tid   = threadIdx.x;
    const int tx    = tid & 15, ty = tid >> 4;

    if (tid < P_DIM) sCarry[tid] = g_carry[c * P_DIM + tid];
    if (tid < 128)   sDv[tid]    = Dg[hbase + tid];
    if (tid == 0)    sFr         = g_chunkFR[c];

    unsigned long long acc[8][4];
#pragma unroll
    for (int r = 0; r < 8; ++r)
#pragma unroll
        for (int q = 0; q < 4; ++q) acc[r][q] = 0ULL;

    __syncthreads();
    const int fr = sFr;
    const float2* Xloc = (const float2*)g_Xlocal;

    for (int ks = 0; ks < 8; ++ks) {
#pragma unroll
        for (int it = 0; it < 4; ++it) {     // stage corrected x: 128t x 8 complex states
            int idx = it * 256 + tid;
            int t = idx >> 3, pp = idx & 7;
            int p = ks * 8 + pp;
            float2 xl = Xloc[(size_t)(c * T_CH + t) * P_DIM + p];
            if (t < fr) {
                float2 ap = g_Apow[t * P_DIM + p];
                float2 cv = sCarry[p];
                xl.x += ap.x * cv.x - ap.y * cv.y;
                xl.y += ap.x * cv.y + ap.y * cv.x;
            }
            sX[(2 * pp + 0) * 132 + t] = xl.x;
            sX[(2 * pp + 1) * 132 + t] = xl.y;
        }
#pragma unroll
        for (int it = 0; it < 2; ++it) {     // stage V: 16k x 128h
            int idx4 = it * 256 + tid;
            int kk = idx4 >> 5, h4 = idx4 & 31;
            *(float4*)&sV[kk * 132 + h4 * 4] =
                *(const float4*)&g_V[(ks * 16 + kk) * H_DIM + hbase + h4 * 4];
        }
        __syncthreads();
#pragma unroll
        for (int kk = 0; kk < 16; ++kk) {
            float4 a0 = *(const float4*)&sX[kk * 132 + ty * 8];       // broadcast
            float4 a1 = *(const float4*)&sX[kk * 132 + ty * 8 + 4];
            unsigned long long b2[4];
#pragma unroll
            for (int q = 0; q < 4; ++q)                               // conflict-free
                b2[q] = *(const unsigned long long*)&sV[kk * 132 + 2 * tx + 32 * q];
            float ar[8] = {a0.x, a0.y, a0.z, a0.w, a1.x, a1.y, a1.z, a1.w};
#pragma unroll
            for (int r = 0; r < 8; ++r) {
                unsigned long long a2 = pack2(ar[r]);
#pragma unroll
                for (int q = 0; q < 4; ++q) ffma2(acc[r][q], a2, b2[q]);
            }
        }
        __syncthreads();
    }

    // epilogue: y = acc + u*D, columns h = 2*tx + 32*q (+0/1), float2 ops (coalesced)
#pragma unroll
    for (int r = 0; r < 8; ++r) {
        size_t t = (size_t)c * T_CH + ty * 8 + r;
#pragma unroll
        for (int q = 0; q < 4; ++q) {
            int hl = 2 * tx + 32 * q;
            float2 uv = *(const float2*)&u[t * H_DIM + hbase + hl];
            float2 a  = unpack2(acc[r][q]);
            float2 o  = make_float2(a.x + uv.x * sDv[hl],
                                    a.y + uv.y * sDv[hl + 1]);
            *(float2*)&y[t * H_DIM + hbase + hl] = o;
        }
    }
}

// ================= launch =================
extern "C" void kernel_launch(void* const* d_in, const int* in_sizes, int n_in,
                              void* d_out, int out_size) {
    (void)in_sizes; (void)n_in; (void)out_size;
    const float* u    = (const float*)d_in[0];
    const float* Lre  = (const float*)d_in[1];
    const float* Lim  = (const float*)d_in[2];
    const float* Bre  = (const float*)d_in[3];
    const float* Bim  = (const float*)d_in[4];
    const float* Cre  = (const float*)d_in[5];
    const float* Cim  = (const float*)d_in[6];
    const float* Dv   = (const float*)d_in[7];
    const float* delt = (const float*)d_in[8];
    const float* x0re = (const float*)d_in[9];
    const float* x0im = (const float*)d_in[10];
    const void*  dfl  = d_in[11];
    float* y = (float*)d_out;

    cudaFuncSetAttribute(kernelA, cudaFuncAttributeMaxDynamicSharedMemorySize, A_TOT);

    zero_flags_kernel<<<1, 1>>>();
    setup_kernel<<<128, 256>>>(Lre, Lim, Bre, Bim, Cre, Cim, delt, (const unsigned*)dfl);
    kernelA<<<NC, 256, A_TOT>>>(u, dfl);
    kernelB<<<P_DIM, NC>>>(x0re, x0im);
    kernelC<<<dim3(NC, 2), 256>>>(u, Dv, y);
}

// round 15
// speedup vs baseline: 1.5264x; 1.1841x over previous
#include <cuda_runtime.h>
#include <cuda_bf16.h>
#include <cstdint>

#define L_SEQ 131072
#define H_DIM 256
#define P_DIM 64
#define J_DIM 128
#define T_CH  128
#define NC    (L_SEQ / T_CH)

// ================= device scratch =================
// W tile images: [K-half][hi/lo] of [128 j rows][136 k cols] bf16 (34816 B each)
__device__ float4 g_WTiles[4 * 2176];
// V tile images: [N-half][hi/lo] of [128 h rows][136 k(j) cols] bf16 (34816 B each)
__device__ float4 g_VTiles[4 * 2176];
__device__ float2 g_Apow[T_CH * P_DIM];             // [t][p] lam^(t+1)
__device__ float2 g_LamBar[P_DIM];
__device__ float4 g_Xlocal[(size_t)L_SEQ * P_DIM / 2];
__device__ float2 g_chunkA[P_DIM * NC];
__device__ float2 g_chunkB[P_DIM * NC];
__device__ int    g_chunkFR[NC];
__device__ float2 g_carry[NC * P_DIM];
__device__ int    g_cntF, g_cntOne, g_cntOther;

// ================= helpers =================
__device__ __forceinline__ float2 cmul(float2 a, float2 b) {
    return make_float2(a.x * b.x - a.y * b.y, a.x * b.y + a.y * b.x);
}
__device__ __forceinline__ float2 cexpf2(float re, float im) {
    float e = expf(re), s, c;
    sincosf(im, &s, &c);
    return make_float2(e * c, e * s);
}
__device__ __forceinline__ int d_mode() {
    if (g_cntF > 0) return 2;
    if (g_cntOther > 0) return 0;
    if (g_cntOne > 0) return 1;
    return 0;
}
__device__ __forceinline__ bool load_d(const void* d, int t, int mode) {
    if (mode == 2) return ((const float*)d)[t] != 0.0f;
    if (mode == 1) return ((const int*)d)[t] != 0;
    return ((const unsigned char*)d)[t] != 0;
}
__device__ __forceinline__ uint32_t split_pair(float a, float b, uint32_t& lo_pack) {
    __nv_bfloat16 ah = __float2bfloat16(a), bh = __float2bfloat16(b);
    float ar = a - __bfloat162float(ah), br = b - __bfloat162float(bh);
    __nv_bfloat16 al = __float2bfloat16(ar), bl = __float2bfloat16(br);
    lo_pack = ((uint32_t)__bfloat16_as_ushort(bl) << 16) | (uint32_t)__bfloat16_as_ushort(al);
    return ((uint32_t)__bfloat16_as_ushort(bh) << 16) | (uint32_t)__bfloat16_as_ushort(ah);
}
__device__ __forceinline__ void mma16816(float c[4], const uint32_t a[4], uint32_t b0, uint32_t b1) {
    asm volatile("mma.sync.aligned.m16n8k16.row.col.f32.bf16.bf16.f32 "
                 "{%0,%1,%2,%3}, {%4,%5,%6,%7}, {%8,%9}, {%0,%1,%2,%3};"
                 : "+f"(c[0]), "+f"(c[1]), "+f"(c[2]), "+f"(c[3])
                 : "r"(a[0]), "r"(a[1]), "r"(a[2]), "r"(a[3]), "r"(b0), "r"(b1));
}
// K=128 pass: A [128][136] bf16 row-major (k contig), B [128 n][136] (k contig). Warp tile 32x64.
__device__ __forceinline__ void mma_pass(const __nv_bfloat16* As, const __nv_bfloat16* Bs,
                                         float acc[2][8][4], int wm, int wn, int gq, int tg) {
#pragma unroll 2
    for (int kk = 0; kk < 8; ++kk) {
        const int k0 = kk * 16 + 2 * tg;
        uint32_t af[2][4];
#pragma unroll
        for (int fm = 0; fm < 2; ++fm) {
            int r = wm * 32 + fm * 16 + gq;
            af[fm][0] = *(const uint32_t*)&As[r * 136 + k0];
            af[fm][1] = *(const uint32_t*)&As[(r + 8) * 136 + k0];
            af[fm][2] = *(const uint32_t*)&As[r * 136 + k0 + 8];
            af[fm][3] = *(const uint32_t*)&As[(r + 8) * 136 + k0 + 8];
        }
#pragma unroll
        for (int fn = 0; fn < 8; ++fn) {
            int n = wn * 64 + fn * 8 + gq;
            uint32_t b0 = *(const uint32_t*)&Bs[n * 136 + k0];
            uint32_t b1 = *(const uint32_t*)&Bs[n * 136 + k0 + 8];
            mma16816(acc[0][fn], af[0], b0, b1);
            mma16816(acc[1][fn], af[1], b0, b1);
        }
    }
}

// ================= kernel 0a =================
__global__ void zero_flags_kernel() { g_cntF = 0; g_cntOne = 0; g_cntOther = 0; }

// ================= kernel 0b: params, split tile images, d sniff =================
__global__ void setup_kernel(const float* __restrict__ Lre, const float* __restrict__ Lim,
                             const float* __restrict__ Bre, const float* __restrict__ Bim,
                             const float* __restrict__ Cre, const float* __restrict__ Cim,
                             const float* __restrict__ deltas,
                             const unsigned* __restrict__ dwords) {
    int g = blockIdx.x * blockDim.x + threadIdx.x;   // 0..32767

    {   // W element (h, j) -> bf16 hi/lo images (rows=j, cols=k=h within K-half)
        int h = g >> 7, j = g & 127, p = j >> 1;
        float lre = Lre[p], lim = Lim[p], dp = deltas[p];
        float2 lb = cexpf2(lre * dp, lim * dp);
        float a = lb.x - 1.0f, bb = lb.y;
        float den = lre * lre + lim * lim;
        float cr = (a * lre + bb * lim) / den;
        float ci = (bb * lre - a * lim) / den;
        float br = Bre[p * H_DIM + h], bi = Bim[p * H_DIM + h];
        float Wv = (j & 1) ? (cr * bi + ci * br) : (cr * br - ci * bi);
        __nv_bfloat16 hi = __float2bfloat16(Wv);
        __nv_bfloat16 lo = __float2bfloat16(Wv - __bfloat162float(hi));
        int kh = h >> 7, col = h & 127;
        char* wb = (char*)g_WTiles;
        uint32_t off = (uint32_t)(kh * 2) * 34816u + (uint32_t)j * 272u + (uint32_t)col * 2u;
        *(__nv_bfloat16*)(wb + off)          = hi;
        *(__nv_bfloat16*)(wb + off + 34816u) = lo;
    }
    {   // V element (j2, h2): V[j][h] = (j odd ? -2*Cim : 2*Cre) -> images rows=h (N), cols=k=j
        int j2 = g >> 8, h2 = g & 255, p = j2 >> 1;
        float Vv = (j2 & 1) ? (-2.0f * Cim[h2 * P_DIM + p]) : (2.0f * Cre[h2 * P_DIM + p]);
        __nv_bfloat16 hi = __float2bfloat16(Vv);
        __nv_bfloat16 lo = __float2bfloat16(Vv - __bfloat162float(hi));
        int nh = h2 >> 7, row = h2 & 127;
        char* vb = (char*)g_VTiles;
        uint32_t off = (uint32_t)(nh * 2) * 34816u + (uint32_t)row * 272u + (uint32_t)j2 * 2u;
        *(__nv_bfloat16*)(vb + off)          = hi;
        *(__nv_bfloat16*)(vb + off + 34816u) = lo;
    }
    if (g < P_DIM) {
        float2 lam = cexpf2(Lre[g] * deltas[g], Lim[g] * deltas[g]);
        g_LamBar[g] = lam;
        float2 a = lam;
        for (int t = 0; t < T_CH; ++t) {
            g_Apow[t * P_DIM + g] = a;   // lam^(t+1)
            a = cmul(a, lam);
        }
    }
    unsigned w = dwords[g];
    if (w) {
        if (w == 0x3F800000u)  atomicAdd(&g_cntF, 1);
        else if (w == 1u)      atomicAdd(&g_cntOne, 1);
        else                   atomicAdd(&g_cntOther, 1);
    }
}

// ================= kernel A: Bu HMMA GEMM + local scan (verbatim R12, proven) =================
// smem: [0..1024) hdr (sD @16); uh @1024; ul @35840; Wb @70656; total 105472.
// sBu (f32 [128][132], 67584 B) overlays uh/ul after the MMAs.
#define A_UH  1024
#define A_UL  (A_UH + 34816)
#define A_WB  (A_UL + 34816)
#define A_TOT (A_WB + 34816)
__global__ __launch_bounds__(256)
void kernelA(const float* __restrict__ u, const void* __restrict__ dflags) {
    extern __shared__ char smem[];
    unsigned char* sD = (unsigned char*)(smem + 16);
    __nv_bfloat16* uh = (__nv_bfloat16*)(smem + A_UH);
    __nv_bfloat16* ul = (__nv_bfloat16*)(smem + A_UL);
    __nv_bfloat16* Wb = (__nv_bfloat16*)(smem + A_WB);
    float* sBu = (float*)(smem + A_UH);

    const int tid = threadIdx.x, wid = tid >> 5, lane = tid & 31;
    const int wm = wid & 3, wn = wid >> 2;
    const int gq = lane >> 2, tg = lane & 3;
    const int c = blockIdx.x;

    if (tid < T_CH) {
        int mode = d_mode();
        sD[tid] = load_d(dflags, c * T_CH + tid, mode) ? 1 : 0;
    }

    float acc[2][8][4];
#pragma unroll
    for (int fm = 0; fm < 2; ++fm)
#pragma unroll
        for (int fn = 0; fn < 8; ++fn)
#pragma unroll
            for (int q = 0; q < 4; ++q) acc[fm][fn][q] = 0.0f;

    for (int kh = 0; kh < 2; ++kh) {
        __syncthreads();
        {   // stage W hi image for this K-half
            const float4* src = g_WTiles + (kh * 2 + 0) * 2176;
            float4* dst = (float4*)(smem + A_WB);
            for (int i = tid; i < 2176; i += 256) dst[i] = src[i];
        }
        // convert u K-half -> uh/ul
        for (int i = tid; i < 4096; i += 256) {
            int t = i >> 5, q = i & 31;
            float4 v = *(const float4*)&u[(size_t)(c * T_CH + t) * H_DIM + kh * 128 + 4 * q];
            uint32_t l0, l1;
            uint32_t h0 = split_pair(v.x, v.y, l0);
            uint32_t h1 = split_pair(v.z, v.w, l1);
            *(uint32_t*)&uh[t * 136 + 4 * q]     = h0;
            *(uint32_t*)&uh[t * 136 + 4 * q + 2] = h1;
            *(uint32_t*)&ul[t * 136 + 4 * q]     = l0;
            *(uint32_t*)&ul[t * 136 + 4 * q + 2] = l1;
        }
        __syncthreads();
        mma_pass(uh, Wb, acc, wm, wn, gq, tg);   // hi*hi
        mma_pass(ul, Wb, acc, wm, wn, gq, tg);   // lo*hi
        __syncthreads();
        {   // stage W lo image
            const float4* src = g_WTiles + (kh * 2 + 1) * 2176;
            float4* dst = (float4*)(smem + A_WB);
            for (int i = tid; i < 2176; i += 256) dst[i] = src[i];
        }
        __syncthreads();
        mma_pass(uh, Wb, acc, wm, wn, gq, tg);   // hi*lo
    }
    __syncthreads();                             // uh/ul dead -> overlay sBu

#pragma unroll
    for (int fm = 0; fm < 2; ++fm) {
        int r0 = wm * 32 + fm * 16 + gq;
#pragma unroll
        for (int fn = 0; fn < 8; ++fn) {
            int nb = wn * 64 + fn * 8 + 2 * tg;
            *(float2*)&sBu[r0 * 132 + nb]       = make_float2(acc[fm][fn][0], acc[fm][fn][1]);
            *(float2*)&sBu[(r0 + 8) * 132 + nb] = make_float2(acc[fm][fn][2], acc[fm][fn][3]);
        }
    }
    __syncthreads();

    if (tid < P_DIM) {                           // sequential local scan
        const int p = tid;
        const float2 lam = g_LamBar[p];
        float2 A = make_float2(1.0f, 0.0f), b = make_float2(0.0f, 0.0f);
        int fr = T_CH;
        float2* xl = (float2*)g_Xlocal;
        for (int tl = 0; tl < T_CH; ++tl) {
            float2 Bu = *(const float2*)&sBu[tl * 132 + 2 * p];
            if (sD[tl]) {
                A = lam; b = Bu;
                if (fr == T_CH) fr = tl;
            } else {
                float2 nA = cmul(lam, A);
                b = make_float2(lam.x * b.x - lam.y * b.y + Bu.x,
                                lam.x * b.y + lam.y * b.x + Bu.y);
                A = nA;
            }
            xl[(size_t)(c * T_CH + tl) * P_DIM + p] = b;
        }
        g_chunkA[p * NC + c] = A;
        g_chunkB[p * NC + c] = b;
        if (p == 0) g_chunkFR[c] = fr;
    }
}

// ================= kernel B: chunk-level Kogge-Stone scan =================
__global__ __launch_bounds__(1024)
void kernelB(const float* __restrict__ x0re, const float* __restrict__ x0im) {
    __shared__ __align__(16) float2 sA[NC];
    __shared__ __align__(16) float2 sB[NC];
    __shared__ unsigned char sDf[NC];
    const int p = blockIdx.x, c = threadIdx.x;

    float2 A = g_chunkA[p * NC + c];
    float2 b = g_chunkB[p * NC + c];
    unsigned char dflag = (g_chunkFR[c] < T_CH) ? 1 : 0;

    if (c == 0 && !dflag) {
        float2 x0 = make_float2(x0re[p], x0im[p]);
        b.x += A.x * x0.x - A.y * x0.y;
        b.y += A.x * x0.y + A.y * x0.x;
    }
    sA[c] = A; sB[c] = b; sDf[c] = dflag;

    for (int off = 1; off < NC; off <<= 1) {
        __syncthreads();
        float2 oA, oB; unsigned char oD = 0;
        bool have = (c >= off);
        if (have) { oA = sA[c - off]; oB = sB[c - off]; oD = sDf[c - off]; }
        __syncthreads();
        if (have && !dflag) {
            b = make_float2(A.x * oB.x - A.y * oB.y + b.x,
                            A.x * oB.y + A.y * oB.x + b.y);
            A = cmul(A, oA);
            dflag = oD;
            sA[c] = A; sB[c] = b; sDf[c] = dflag;
        }
    }
    __syncthreads();
    float2 cv = (c == 0) ? make_float2(x0re[p], x0im[p]) : sB[c - 1];
    g_carry[c * P_DIM + p] = cv;
}

// ================= kernel C: HMMA, 1-D grid, conversion shared across both N-halves ====
// smem: [0..2048) hdr (fr @16, sCarry @64 (512B), sDv @576 (1024B, all 256 D));
//       xh @2048; xl @36864; Vb @71680; total 106496. No overlays.
#define C_XH  2048
#define C_XL  (C_XH + 34816)
#define C_VB  (C_XL + 34816)
#define C_TOT (C_VB + 34816)
__global__ __launch_bounds__(256)
void kernelC(const float* __restrict__ u, const float* __restrict__ Dg, float* __restrict__ y) {
    extern __shared__ char smem[];
    float2* sCarry = (float2*)(smem + 64);
    float*  sDv    = (float*)(smem + 576);
    __nv_bfloat16* xh = (__nv_bfloat16*)(smem + C_XH);
    __nv_bfloat16* xl = (__nv_bfloat16*)(smem + C_XL);
    __nv_bfloat16* Vb = (__nv_bfloat16*)(smem + C_VB);

    const int tid = threadIdx.x, wid = tid >> 5, lane = tid & 31;
    const int wm = wid & 3, wn = wid >> 2;
    const int gq = lane >> 2, tg = lane & 3;
    const int c = blockIdx.x;

    if (tid == 0) *(int*)(smem + 16) = g_chunkFR[c];
    if (tid < P_DIM) sCarry[tid] = g_carry[c * P_DIM + tid];
    sDv[tid] = Dg[tid];                          // all 256 D values
    __syncthreads();
    const int fr = *(const int*)(smem + 16);

    // corrected x -> xh/xl once (float2 reads, R12-C access pattern; correction fused)
    {
        const float2* Xloc = (const float2*)g_Xlocal;
        for (int i = tid; i < 4096; i += 256) {
            int t = i >> 5, q = i & 31;
            int p0 = 2 * q, p1 = 2 * q + 1;
            size_t base = (size_t)(c * T_CH + t) * P_DIM;
            float2 v0 = Xloc[base + p0];
            float2 v1 = Xloc[base + p1];
            if (t < fr) {
                float2 a0 = g_Apow[t * P_DIM + p0], a1 = g_Apow[t * P_DIM + p1];
                float2 c0 = sCarry[p0], c1 = sCarry[p1];
                v0.x += a0.x * c0.x - a0.y * c0.y;
                v0.y += a0.x * c0.y + a0.y * c0.x;
                v1.x += a1.x * c1.x - a1.y * c1.y;
                v1.y += a1.x * c1.y + a1.y * c1.x;
            }
            uint32_t l0, l1;
            uint32_t h0 = split_pair(v0.x, v0.y, l0);
            uint32_t h1 = split_pair(v1.x, v1.y, l1);
            *(uint32_t*)&xh[t * 136 + 4 * q]     = h0;
            *(uint32_t*)&xh[t * 136 + 4 * q + 2] = h1;
            *(uint32_t*)&xl[t * 136 + 4 * q]     = l0;
            *(uint32_t*)&xl[t * 136 + 4 * q + 2] = l1;
        }
    }

    for (int nh = 0; nh < 2; ++nh) {
        const int hbase = nh * 128;
        __syncthreads();                         // conversion done / prev-nh Vb readers done
        {   // stage V hi image for this N-half (clone of kernelA W staging)
            const float4* src = g_VTiles + (nh * 2 + 0) * 2176;
            float4* dst = (float4*)(smem + C_VB);
            for (int i = tid; i < 2176; i += 256) dst[i] = src[i];
        }
        __syncthreads();

        float acc[2][8][4];
#pragma unroll
        for (int fm = 0; fm < 2; ++fm)
#pragma unroll
            for (int fn = 0; fn < 8; ++fn)
#pragma unroll
                for (int q = 0; q < 4; ++q) acc[fm][fn][q] = 0.0f;

        mma_pass(xh, Vb, acc, wm, wn, gq, tg);   // hi*hi
        mma_pass(xl, Vb, acc, wm, wn, gq, tg);   // lo*hi
        __syncthreads();
        {   // stage V lo image
            const float4* src = g_VTiles + (nh * 2 + 1) * 2176;
            float4* dst = (float4*)(smem + C_VB);
            for (int i = tid; i < 2176; i += 256) dst[i] = src[i];
        }
        __syncthreads();
        mma_pass(xh, Vb, acc, wm, wn, gq, tg);   // hi*lo

        // epilogue: direct register -> global (R12-C pattern), y = acc + u*D
#pragma unroll
        for (int fm = 0; fm < 2; ++fm) {
            int r0 = wm * 32 + fm * 16 + gq;
            size_t t0 = (size_t)c * T_CH + r0;
#pragma unroll
            for (int fn = 0; fn < 8; ++fn) {
                int nb = wn * 64 + fn * 8 + 2 * tg;
                float dv0 = sDv[hbase + nb], dv1 = sDv[hbase + nb + 1];
                float2 u0 = *(const float2*)&u[t0 * H_DIM + hbase + nb];
                float2 u1 = *(const float2*)&u[(t0 + 8) * H_DIM + hbase + nb];
                *(float2*)&y[t0 * H_DIM + hbase + nb] =
                    make_float2(acc[fm][fn][0] + u0.x * dv0, acc[fm][fn][1] + u0.y * dv1);
                *(float2*)&y[(t0 + 8) * H_DIM + hbase + nb] =
                    make_float2(acc[fm][fn][2] + u1.x * dv0, acc[fm][fn][3] + u1.y * dv1);
            }
        }
    }
}

// ================= launch =================
extern "C" void kernel_launch(void* const* d_in, const int* in_sizes, int n_in,
                              void* d_out, int out_size) {
    (void)in_sizes; (void)n_in; (void)out_size;
    const float* u    = (const float*)d_in[0];
    const float* Lre  = (const float*)d_in[1];
    const float* Lim  = (const float*)d_in[2];
    const float* Bre  = (const float*)d_in[3];
    const float* Bim  = (const float*)d_in[4];
    const float* Cre  = (const float*)d_in[5];
    const float* Cim  = (const float*)d_in[6];
    const float* Dv   = (const float*)d_in[7];
    const float* delt = (const float*)d_in[8];
    const float* x0re = (const float*)d_in[9];
    const float* x0im = (const float*)d_in[10];
    const void*  dfl  = d_in[11];
    float* y = (float*)d_out;

    cudaFuncSetAttribute(kernelA, cudaFuncAttributeMaxDynamicSharedMemorySize, A_TOT);
    cudaFuncSetAttribute(kernelC, cudaFuncAttributeMaxDynamicSharedMemorySize, C_TOT);

    zero_flags_kernel<<<1, 1>>>();
    setup_kernel<<<128, 256>>>(Lre, Lim, Bre, Bim, Cre, Cim, delt, (const unsigned*)dfl);
    kernelA<<<NC, 256, A_TOT>>>(u, dfl);
    kernelB<<<P_DIM, NC>>>(x0re, x0im);
    kernelC<<<NC, 256, C_TOT>>>(u, Dv, y);
}